// round 5
// baseline (speedup 1.0000x reference)
#include <cuda_runtime.h>
#include <cstdint>
#include <cstddef>

// HugeNet: 10000 x (Linear(100,100)+ReLU) scan, then Linear(100,10).
//
// Round 5: intra-warp k-split (4-way) reduced with 2x shfl_xor -> ONE
// __syncthreads per layer, no smem reduction buffer. W streamed to
// registers from thread-interleaved fp32 layout. 64 CTAs x 4 rows,
// 256 threads.
//
// Thread map: kq = lane&3 (k-groups {0:28,28:52,52:76,76:100}),
//             m  = warp*8 + ((lane>>2)&7)  (column pair, m<50 useful)
// Each thread: J=2 columns (2m, 2m+1) x 4 rows over its k-group.

#define N_LAYERS 10000
#define D        100
#define D_OUT    10
#define BATCH    256
#define ROWS     4
#define NCTA     (BATCH / ROWS)   // 64
#define THREADS  256
#define HSTR     104              // h row stride: 416B, 16B-aligned
#define WSLOTS   14               // max float4 per thread per layer (kq0: 2*7)

typedef unsigned long long ull;

// [(N_LAYERS+2)][WSLOTS][256] float4 (~573MB, zero-padded)
__device__ __align__(16) float4 g_Wp[(size_t)(N_LAYERS + 2) * WSLOTS * THREADS];

__host__ __device__ __forceinline__ int kq_base(int kq) {
    return (kq == 0) ? 0 : (28 + 24 * (kq - 1));   // {0,28,52,76}
}
__host__ __device__ __forceinline__ int kq_nq(int kq) {
    return (kq == 0) ? 7 : 6;
}
__host__ __device__ __forceinline__ void tmap(int t, int& m, int& kq) {
    kq = t & 3;
    m  = (t >> 5) * 8 + ((t >> 2) & 7);
}

// ---------------------------------------------------------------------------
// prep: W[l][j][k] row-major -> g_Wp[(l*WSLOTS + i)*256 + t]
//   i = 2q+jj; j = 2m+jj; k = kq_base(kq)+4q
// ---------------------------------------------------------------------------
__global__ void prep_kernel(const float* __restrict__ W) {
    size_t idx = (size_t)blockIdx.x * blockDim.x + threadIdx.x;
    const size_t total = (size_t)(N_LAYERS + 2) * WSLOTS * THREADS;
    if (idx >= total) return;
    int    t    = (int)(idx & (THREADS - 1));
    size_t rest = idx >> 8;
    int    i    = (int)(rest % WSLOTS);
    size_t l    = rest / WSLOTS;
    int m, kq;  tmap(t, m, kq);
    int jj = i & 1, q = i >> 1;
    int j  = 2 * m + jj;
    int k  = kq_base(kq) + 4 * q;
    float4 v = make_float4(0.f, 0.f, 0.f, 0.f);
    if (l < N_LAYERS && j < D && q < kq_nq(kq))
        v = *reinterpret_cast<const float4*>(
                W + l * (size_t)(D * D) + (size_t)j * D + k);
    g_Wp[idx] = v;
}

// ---------------------------------------------------------------------------
__device__ __forceinline__ void fma2(ull& a, ull x, ull y) {
    asm("fma.rn.f32x2 %0, %1, %2, %0;" : "+l"(a) : "l"(x), "l"(y));
}
__device__ __forceinline__ float2 upk(ull v) {
    float2 r;
    asm("mov.b64 {%0, %1}, %2;" : "=f"(r.x), "=f"(r.y) : "l"(v));
    return r;
}

__global__ void __launch_bounds__(THREADS, 1)
hugenet_kernel(const float* __restrict__ x,
               const float* __restrict__ bg,
               const float* __restrict__ Wo,
               const float* __restrict__ bo,
               float* __restrict__ out) {
    __shared__ float h[2][ROWS][HSTR];

    const int tid = threadIdx.x;
    int m, kq;  tmap(tid, m, kq);
    const int nq = kq_nq(kq);
    const int kb = kq_base(kq);
    const int r0 = blockIdx.x * ROWS;
    const bool writer = (kq == 0) && (m < 50);

    for (int idx = tid; idx < ROWS * D; idx += THREADS) {
        int r = idx / D, k = idx % D;
        h[0][r][k] = x[(size_t)(r0 + r) * D + k];
    }
    __syncthreads();

    float4 Wa[WSLOTS], Wb[WSLOTS];

    auto ldW = [&](float4* R, int l) {
        const float4* p = g_Wp + (size_t)l * WSLOTS * THREADS + tid;
        #pragma unroll
        for (int i = 0; i < WSLOTS; i++)
            if (i < 2 * nq) R[i] = __ldg(p + (size_t)i * THREADS);
    };

    float2 bias_a = make_float2(0.f, 0.f), bias_b = make_float2(0.f, 0.f);
    auto ldB = [&](float2& bb, int l) {
        if (writer && l < N_LAYERS)
            bb = *reinterpret_cast<const float2*>(bg + (size_t)l * D + 2 * m);
    };

    auto do_layer = [&](const float4* R, float2 bias, int HB) {
        ull a[8];                          // [jj*4 + r]
        #pragma unroll
        for (int i = 0; i < 8; i++) a[i] = 0ull;

        #pragma unroll
        for (int q = 0; q < 7; q++) {
            if (q < nq) {
                ulonglong2 w0 = *reinterpret_cast<const ulonglong2*>(&R[2 * q]);
                ulonglong2 w1 = *reinterpret_cast<const ulonglong2*>(&R[2 * q + 1]);
                #pragma unroll
                for (int r = 0; r < ROWS; r++) {
                    ulonglong2 hv =
                        *reinterpret_cast<const ulonglong2*>(&h[HB][r][kb + 4 * q]);
                    fma2(a[r],     hv.x, w0.x);
                    fma2(a[r],     hv.y, w0.y);
                    fma2(a[4 + r], hv.x, w1.x);
                    fma2(a[4 + r], hv.y, w1.y);
                }
            }
        }

        float s[8];
        #pragma unroll
        for (int i = 0; i < 8; i++) {
            float2 u = upk(a[i]);
            s[i] = u.x + u.y;
        }
        // reduce across the 4 kq lanes (lanes .., +1, +2, +3)
        #pragma unroll
        for (int i = 0; i < 8; i++)
            s[i] += __shfl_xor_sync(0xffffffffu, s[i], 1);
        #pragma unroll
        for (int i = 0; i < 8; i++)
            s[i] += __shfl_xor_sync(0xffffffffu, s[i], 2);

        if (writer) {
            #pragma unroll
            for (int r = 0; r < ROWS; r++) {
                float v0 = fmaxf(s[r]     + bias.x, 0.f);
                float v1 = fmaxf(s[4 + r] + bias.y, 0.f);
                *reinterpret_cast<float2*>(&h[HB ^ 1][r][2 * m]) =
                    make_float2(v0, v1);
            }
        }
        __syncthreads();
    };

    ldW(Wa, 0);
    ldB(bias_a, 0);

    #pragma unroll 1
    for (int l = 0; l < N_LAYERS; l += 2) {
        ldW(Wb, l + 1);
        ldB(bias_b, l + 1);

        do_layer(Wa, bias_a, 0);           // h[0] -> h[1]

        ldW(Wa, l + 2);                    // pad layers zeroed
        ldB(bias_a, l + 2);

        do_layer(Wb, bias_b, 1);           // h[1] -> h[0]
    }

    // Final Linear(100, 10): 40 threads, one (row, out-col) each. h in h[0].
    if (tid < ROWS * D_OUT) {
        int r = tid / D_OUT, o = tid % D_OUT;
        const float* hr = h[0][r];
        float acc = bo[o];
        #pragma unroll
        for (int k = 0; k < D; k++)
            acc += hr[k] * __ldg(&Wo[(size_t)o * D + k]);
        out[(size_t)(r0 + r) * D_OUT + o] = acc;
    }
}

// ---------------------------------------------------------------------------
extern "C" void kernel_launch(void* const* d_in, const int* in_sizes, int n_in,
                              void* d_out, int out_size) {
    const float *x = nullptr, *W = nullptr, *b = nullptr, *Wo = nullptr, *bo = nullptr;
    for (int i = 0; i < n_in; i++) {
        switch (in_sizes[i]) {
            case 25600:     x  = (const float*)d_in[i]; break;
            case 100000000: W  = (const float*)d_in[i]; break;
            case 1000000:   b  = (const float*)d_in[i]; break;
            case 1000:      Wo = (const float*)d_in[i]; break;
            case 10:        bo = (const float*)d_in[i]; break;
            default: break;
        }
    }

    const size_t total = (size_t)(N_LAYERS + 2) * WSLOTS * THREADS;
    int blocks = (int)((total + 255) / 256);
    prep_kernel<<<blocks, 256>>>(W);

    hugenet_kernel<<<NCTA, THREADS>>>(x, b, Wo, bo, (float*)d_out);
}